// round 10
// baseline (speedup 1.0000x reference)
#include <cuda_runtime.h>
#include <math.h>

#define BB 64
#define NN 4096
#define FF 512
#define KK 128
#define QSZ (BB*KK*KK)

// ---------------- output layout (flattened tuple, float32, reference order) ----
// new_Q [B,K,K] | policy_score [B] | scorer [B,F] | entropy [B] | topk_idx [B,K]
#define OUT_Q      0
#define OUT_POL    (QSZ)
#define OUT_SCORER (QSZ + BB)
#define OUT_ENT    (QSZ + BB + BB*FF)
#define OUT_IDX    (QSZ + BB + BB*FF + BB)
#define OUT_FULL   (QSZ + BB + BB*FF + BB + BB*KK)

// ---------------- device scratch (no cudaMalloc allowed) ----------------
__device__ float g_scorer[BB*FF];
__device__ float g_scores[BB*NN];     // raw (unnormalized) scores
__device__ int   g_idx[BB*KK];
__device__ float g_tv[BB*KK];         // tanh(normalized topk score)
__device__ float g_z[QSZ];            // z_topk, [b][f][j]
__device__ float g_upd[QSZ];
__device__ float g_rst[QSZ];
__device__ float g_ah[QSZ];           // W_h @ z

__device__ __forceinline__ float warpsum(float v) {
    #pragma unroll
    for (int o = 16; o; o >>= 1) v += __shfl_xor_sync(0xffffffffu, v, o);
    return v;
}

// ---------------- K1: scorer[b,f] = tanh(ht[b,:] . W_map[f,:] + b_map[f]) ----
// one warp per (b,f); 8 warps/block; grid = 64*512/8 = 4096
__global__ void k_scorer(const float* __restrict__ ht,
                         const float* __restrict__ W_map,
                         const float* __restrict__ b_map,
                         float* __restrict__ out, int wr_scorer) {
    int w    = (blockIdx.x * blockDim.x + threadIdx.x) >> 5;
    int lane = threadIdx.x & 31;
    int b = w >> 9;          // 512 f per batch
    int f = w & 511;
    const float4* w4 = (const float4*)(W_map + (size_t)f * FF);
    const float4* h4 = (const float4*)(ht    + (size_t)b * FF);   // D == 512
    float s = 0.f;
    #pragma unroll
    for (int i = 0; i < 4; i++) {
        float4 a = w4[lane + 32*i], hh = h4[lane + 32*i];
        s += a.x*hh.x + a.y*hh.y + a.z*hh.z + a.w*hh.w;
    }
    s = warpsum(s);
    if (lane == 0) {
        float v = tanhf(s + b_map[f]);
        g_scorer[b*FF + f] = v;
        if (wr_scorer) out[OUT_SCORER + b*FF + f] = v;
    }
}

// ---------------- K2: raw scores[b,n] = prev_Z[b,n,:] . scorer[b,:] ----------
// one warp per node, 8 nodes/block; grid = 64*512 = 32768. Streams 512 MB.
__global__ void k_scores(const float* __restrict__ prev_Z) {
    __shared__ float sc[FF];
    int b  = blockIdx.x >> 9;                // 512 blocks per batch
    int n0 = (blockIdx.x & 511) * 8;
    int tid = threadIdx.x;
    sc[tid]       = g_scorer[b*FF + tid];
    sc[tid + 256] = g_scorer[b*FF + tid + 256];
    __syncthreads();
    int warp = tid >> 5, lane = tid & 31;
    int n = n0 + warp;
    const float4* zp = (const float4*)(prev_Z + ((size_t)b*NN + n) * FF);
    const float4* c4 = (const float4*)sc;
    float s = 0.f;
    #pragma unroll
    for (int i = 0; i < 4; i++) {
        float4 zv = zp[lane + 32*i], cv = c4[lane + 32*i];
        s += zv.x*cv.x + zv.y*cv.y + zv.z*cv.z + zv.w*cv.w;
    }
    s = warpsum(s);
    if (lane == 0) g_scores[b*NN + n] = s;
}

// ---------------- K3: norm + per-batch full bitonic sort (desc, tie->low idx) -
// grid = 64, block = 1024. Also computes softmax stats / entropy / policy.
__global__ void __launch_bounds__(1024) k_topk(float* __restrict__ out,
                                               int wr_pol, int wr_ent, int wr_idx) {
    __shared__ float  sv[NN];
    __shared__ int    si[NN];
    __shared__ float2 red[1024];
    __shared__ float  s_inv;
    int b = blockIdx.x, tid = threadIdx.x;

    // ---- inverse L2 norm of scorer row b ----
    {
        float v = 0.f;
        if (tid < FF) { float x = g_scorer[b*FF + tid]; v = x * x; }
        red[tid].x = v;
        __syncthreads();
        for (int s = 512; s; s >>= 1) {
            if (tid < s) red[tid].x += red[tid + s].x;
            __syncthreads();
        }
        if (tid == 0) s_inv = rsqrtf(red[0].x);
        __syncthreads();
    }
    float inv = s_inv;

    for (int i = tid; i < NN; i += 1024) { sv[i] = g_scores[b*NN + i] * inv; si[i] = i; }
    __syncthreads();
    for (int k = 2; k <= NN; k <<= 1) {
        for (int j = k >> 1; j > 0; j >>= 1) {
            for (int t = tid; t < NN; t += 1024) {
                int l = t ^ j;
                if (l > t) {
                    float a = sv[t], c = sv[l];
                    int  ia = si[t], ib = si[l];
                    bool desc = ((t & k) == 0);
                    bool sw = desc ? (a < c || (a == c && ia > ib))
                                   : (a > c || (a == c && ia < ib));
                    if (sw) { sv[t] = c; sv[l] = a; si[t] = ib; si[l] = ia; }
                }
            }
            __syncthreads();
        }
    }
    float m = sv[0];                  // global max (sorted desc)
    float se = 0.f, sxe = 0.f;
    for (int i = tid; i < NN; i += 1024) {
        float y = sv[i] - m;
        float e = expf(y);
        se += e; sxe += y * e;
    }
    red[tid] = make_float2(se, sxe);
    __syncthreads();
    for (int s = 512; s; s >>= 1) {
        if (tid < s) { red[tid].x += red[tid+s].x; red[tid].y += red[tid+s].y; }
        __syncthreads();
    }
    if (tid < KK) {
        g_idx[b*KK + tid] = si[tid];
        g_tv[b*KK + tid]  = tanhf(sv[tid]);
        if (wr_idx) out[OUT_IDX + b*KK + tid] = (float)si[tid];
    }
    // policy sum over top-128 vals: warp 0 parallel reduction (4 vals/lane)
    if ((tid >> 5) == 0 && wr_pol) {
        float ps = sv[tid] + sv[tid + 32] + sv[tid + 64] + sv[tid + 96];
        ps = warpsum(ps);
        if (tid == 0) {
            float S = red[0].x, logZ = logf(S);
            out[OUT_POL + b] = ps / (float)KK - m - logZ;
        }
    }
    if (tid == 0 && wr_ent) {
        float S = red[0].x, logZ = logf(S);
        out[OUT_ENT + b] = logZ - red[0].y / S;     // entropy
    }
}

// ---------------- K4: gather + transpose: z[b][f][j] = Z[b,idx_j,f]*tanh(v_j) -
__global__ void k_gather(const float* __restrict__ prev_Z) {
    __shared__ float tile[64][129];
    __shared__ int   sidx[KK];
    __shared__ float stv[KK];
    int b = blockIdx.x, tid = threadIdx.x;     // 256 threads
    if (tid < KK) { sidx[tid] = g_idx[b*KK + tid]; stv[tid] = g_tv[b*KK + tid]; }
    for (int half = 0; half < 2; half++) {
        __syncthreads();
        for (int e = tid; e < 64*128; e += 256) {
            int jj = e >> 7, f = e & 127;
            int j = half*64 + jj;
            tile[jj][f] = prev_Z[((size_t)b*NN + sidx[j]) * FF + f] * stv[j];
        }
        __syncthreads();
        for (int e = tid; e < 128*64; e += 256) {
            int f = e >> 6, jj = e & 63;
            g_z[(size_t)b*16384 + f*128 + half*64 + jj] = tile[jj][f];
        }
    }
}

// ---------------- GEMM helpers: 128x64 tile, K=128, 256 threads ----------------
#define MT_LD 129
#define XS_LD 68
#define SM_GEMM ((128*MT_LD + 128*XS_LD) * 4)

__device__ __forceinline__ void gemm_pass(const float* __restrict__ M,
                                          const float* __restrict__ Xsrc,
                                          int half, float* Mt, float* Xs,
                                          float acc[8][4], int tx, int ty, int tid) {
    // load weight transposed + X tile
    for (int e = tid; e < 128*128; e += 256) {
        int i = e >> 7, k = e & 127;
        Mt[k*MT_LD + i] = M[i*128 + k];
    }
    for (int e = tid; e < 128*64; e += 256) {
        int k = e >> 6, j = e & 63;
        Xs[k*XS_LD + j] = Xsrc[k*128 + half*64 + j];
    }
    __syncthreads();
    #pragma unroll 8
    for (int k = 0; k < 128; k++) {
        float4 xv = *(const float4*)&Xs[k*XS_LD + tx*4];
        float w[8];
        #pragma unroll
        for (int r = 0; r < 8; r++) w[r] = Mt[k*MT_LD + ty*8 + r];
        #pragma unroll
        for (int r = 0; r < 8; r++) {
            acc[r][0] += w[r]*xv.x; acc[r][1] += w[r]*xv.y;
            acc[r][2] += w[r]*xv.z; acc[r][3] += w[r]*xv.w;
        }
    }
    __syncthreads();
}

// ---------------- K5: update/reset gates + Ah = W_h @ z ----------------
// grid = 3 gates * 64 batches * 2 col-halves = 384
__global__ void __launch_bounds__(256) k_gates(
        const float* __restrict__ W_u, const float* __restrict__ U_u, const float* __restrict__ b_u,
        const float* __restrict__ W_r, const float* __restrict__ U_r, const float* __restrict__ b_r,
        const float* __restrict__ W_h, const float* __restrict__ prev_Q) {
    extern __shared__ float sm[];
    float* Mt = sm;
    float* Xs = sm + 128*MT_LD;
    int gate = blockIdx.x >> 7;
    int rem  = blockIdx.x & 127;
    int b = rem >> 1, half = rem & 1;
    int tid = threadIdx.x, tx = tid & 15, ty = tid >> 4;
    float acc[8][4];
    #pragma unroll
    for (int r = 0; r < 8; r++)
        #pragma unroll
        for (int c = 0; c < 4; c++) acc[r][c] = 0.f;

    const float* z = g_z + (size_t)b*16384;
    const float* Q = prev_Q + (size_t)b*16384;

    if (gate == 0) {
        gemm_pass(W_u, z, half, Mt, Xs, acc, tx, ty, tid);
        gemm_pass(U_u, Q, half, Mt, Xs, acc, tx, ty, tid);
    } else if (gate == 1) {
        gemm_pass(W_r, z, half, Mt, Xs, acc, tx, ty, tid);
        gemm_pass(U_r, Q, half, Mt, Xs, acc, tx, ty, tid);
    } else {
        gemm_pass(W_h, z, half, Mt, Xs, acc, tx, ty, tid);
    }

    size_t base = (size_t)b * 16384;
    #pragma unroll
    for (int r = 0; r < 8; r++) {
        int i = ty*8 + r;
        #pragma unroll
        for (int c = 0; c < 4; c++) {
            int j = half*64 + tx*4 + c;
            float p = acc[r][c];
            if (gate == 0) {
                p += b_u[i*128 + j];
                g_upd[base + i*128 + j] = 1.f / (1.f + expf(-p));
            } else if (gate == 1) {
                p += b_r[i*128 + j];
                g_rst[base + i*128 + j] = 1.f / (1.f + expf(-p));
            } else {
                g_ah[base + i*128 + j] = p;
            }
        }
    }
}

// ---------------- K6: h_cap = tanh(Ah + U_h@(r*Q) + b_h); new_Q -------------
// grid = 64 batches * 2 halves = 128
__global__ void __launch_bounds__(256) k_final(
        const float* __restrict__ U_h, const float* __restrict__ b_h,
        const float* __restrict__ prev_Q, float* __restrict__ out) {
    extern __shared__ float sm[];
    float* Mt = sm;
    float* Xs = sm + 128*MT_LD;
    int b = blockIdx.x >> 1, half = blockIdx.x & 1;
    int tid = threadIdx.x, tx = tid & 15, ty = tid >> 4;
    float acc[8][4];
    #pragma unroll
    for (int r = 0; r < 8; r++)
        #pragma unroll
        for (int c = 0; c < 4; c++) acc[r][c] = 0.f;

    size_t base = (size_t)b * 16384;
    // load Mt + X = reset .* prev_Q on the fly
    for (int e = tid; e < 128*128; e += 256) {
        int i = e >> 7, k = e & 127;
        Mt[k*MT_LD + i] = U_h[i*128 + k];
    }
    for (int e = tid; e < 128*64; e += 256) {
        int k = e >> 6, j = e & 63;
        int g = k*128 + half*64 + j;
        Xs[k*XS_LD + j] = g_rst[base + g] * prev_Q[base + g];
    }
    __syncthreads();
    #pragma unroll 8
    for (int k = 0; k < 128; k++) {
        float4 xv = *(const float4*)&Xs[k*XS_LD + tx*4];
        float w[8];
        #pragma unroll
        for (int r = 0; r < 8; r++) w[r] = Mt[k*MT_LD + ty*8 + r];
        #pragma unroll
        for (int r = 0; r < 8; r++) {
            acc[r][0] += w[r]*xv.x; acc[r][1] += w[r]*xv.y;
            acc[r][2] += w[r]*xv.z; acc[r][3] += w[r]*xv.w;
        }
    }
    #pragma unroll
    for (int r = 0; r < 8; r++) {
        int i = ty*8 + r;
        #pragma unroll
        for (int c = 0; c < 4; c++) {
            int j = half*64 + tx*4 + c;
            size_t idx = base + i*128 + j;
            float h = tanhf(acc[r][c] + g_ah[idx] + b_h[i*128 + j]);
            float u = g_upd[idx];
            float q = prev_Q[idx];
            out[OUT_Q + idx] = (1.f - u)*q + u*h;
        }
    }
}

// ---------------- host ----------------
extern "C" void kernel_launch(void* const* d_in, const int* in_sizes, int n_in,
                              void* d_out, int out_size) {
    const float* prev_Q = (const float*)d_in[0];
    const float* prev_Z = (const float*)d_in[1];
    const float* ht     = (const float*)d_in[2];
    const float* W_map  = (const float*)d_in[3];
    const float* b_map  = (const float*)d_in[4];
    const float* W_u    = (const float*)d_in[5];
    const float* U_u    = (const float*)d_in[6];
    const float* b_u    = (const float*)d_in[7];
    const float* W_r    = (const float*)d_in[8];
    const float* U_r    = (const float*)d_in[9];
    const float* b_r    = (const float*)d_in[10];
    const float* W_h    = (const float*)d_in[11];
    const float* U_h    = (const float*)d_in[12];
    const float* b_h    = (const float*)d_in[13];
    float* out = (float*)d_out;

    // per-section guards: write a section only if out_size covers it
    int wr_pol    = (out_size >= OUT_SCORER) ? 1 : 0;
    int wr_scorer = (out_size >= OUT_ENT)    ? 1 : 0;
    int wr_ent    = (out_size >= OUT_IDX)    ? 1 : 0;
    int wr_idx    = (out_size >= OUT_FULL)   ? 1 : 0;

    // no static guards (harness rule): idempotent, called every time
    cudaFuncSetAttribute(k_gates, cudaFuncAttributeMaxDynamicSharedMemorySize, SM_GEMM);
    cudaFuncSetAttribute(k_final, cudaFuncAttributeMaxDynamicSharedMemorySize, SM_GEMM);

    k_scorer <<<(BB*FF)/8, 256>>>(ht, W_map, b_map, out, wr_scorer);
    k_scores <<<BB*(NN/8), 256>>>(prev_Z);
    k_topk   <<<BB, 1024>>>(out, wr_pol, wr_ent, wr_idx);
    k_gather <<<BB, 256>>>(prev_Z);
    k_gates  <<<384, 256, SM_GEMM>>>(W_u, U_u, b_u, W_r, U_r, b_r, W_h, prev_Q);
    k_final  <<<128, 256, SM_GEMM>>>(U_h, b_h, prev_Q, out);
}

// round 13
// speedup vs baseline: 1.2946x; 1.2946x over previous
#include <cuda_runtime.h>
#include <math.h>

#define BB 64
#define NN 4096
#define FF 512
#define KK 128
#define QSZ (BB*KK*KK)

// ---------------- output layout (flattened tuple, float32, reference order) ----
// new_Q [B,K,K] | policy_score [B] | scorer [B,F] | entropy [B] | topk_idx [B,K]
#define OUT_Q      0
#define OUT_POL    (QSZ)
#define OUT_SCORER (QSZ + BB)
#define OUT_ENT    (QSZ + BB + BB*FF)
#define OUT_IDX    (QSZ + BB + BB*FF + BB)
#define OUT_FULL   (QSZ + BB + BB*FF + BB + BB*KK)

// ---------------- device scratch (no cudaMalloc allowed) ----------------
__device__ float g_scorer[BB*FF];
__device__ float g_scores[BB*NN];     // raw (unnormalized) scores
__device__ int   g_idx[BB*KK];
__device__ float g_tv[BB*KK];         // tanh(normalized topk score)
__device__ float g_z[QSZ];            // z_topk, [b][f][j]
__device__ float g_upd[QSZ];
__device__ float g_rst[QSZ];
__device__ float g_ah[QSZ];           // W_h @ z

__device__ __forceinline__ float warpsum(float v) {
    #pragma unroll
    for (int o = 16; o; o >>= 1) v += __shfl_xor_sync(0xffffffffu, v, o);
    return v;
}

// ordered-float map: u(v) monotone ascending in v
__device__ __forceinline__ unsigned int f2ord(float v) {
    unsigned int u = __float_as_uint(v);
    return u ^ ((u >> 31) ? 0xFFFFFFFFu : 0x80000000u);
}
__device__ __forceinline__ float ord2f(unsigned int u) {
    unsigned int bits = (u & 0x80000000u) ? (u ^ 0x80000000u) : ~u;
    return __uint_as_float(bits);
}
// key decode: value from packed key (high 32 bits hold ~u)
__device__ __forceinline__ float key2val(unsigned long long k) {
    return ord2f(~(unsigned int)(k >> 32));
}

// ---------------- K1: scorer[b,f] = tanh(ht[b,:] . W_map[f,:] + b_map[f]) ----
// one warp per (b,f); 8 warps/block; grid = 64*512/8 = 4096
__global__ void k_scorer(const float* __restrict__ ht,
                         const float* __restrict__ W_map,
                         const float* __restrict__ b_map,
                         float* __restrict__ out, int wr_scorer) {
    int w    = (blockIdx.x * blockDim.x + threadIdx.x) >> 5;
    int lane = threadIdx.x & 31;
    int b = w >> 9;          // 512 f per batch
    int f = w & 511;
    const float4* w4 = (const float4*)(W_map + (size_t)f * FF);
    const float4* h4 = (const float4*)(ht    + (size_t)b * FF);   // D == 512
    float s = 0.f;
    #pragma unroll
    for (int i = 0; i < 4; i++) {
        float4 a = w4[lane + 32*i], hh = h4[lane + 32*i];
        s += a.x*hh.x + a.y*hh.y + a.z*hh.z + a.w*hh.w;
    }
    s = warpsum(s);
    if (lane == 0) {
        float v = tanhf(s + b_map[f]);
        g_scorer[b*FF + f] = v;
        if (wr_scorer) out[OUT_SCORER + b*FF + f] = v;
    }
}

// ---------------- K2: raw scores[b,n] = prev_Z[b,n,:] . scorer[b,:] ----------
// one warp per node, 8 nodes/block; grid = 64*512 = 32768. Streams 512 MB.
__global__ void k_scores(const float* __restrict__ prev_Z) {
    __shared__ float sc[FF];
    int b  = blockIdx.x >> 9;                // 512 blocks per batch
    int n0 = (blockIdx.x & 511) * 8;
    int tid = threadIdx.x;
    sc[tid]       = g_scorer[b*FF + tid];
    sc[tid + 256] = g_scorer[b*FF + tid + 256];
    __syncthreads();
    int warp = tid >> 5, lane = tid & 31;
    int n = n0 + warp;
    const float4* zp = (const float4*)(prev_Z + ((size_t)b*NN + n) * FF);
    const float4* c4 = (const float4*)sc;
    float s = 0.f;
    #pragma unroll
    for (int i = 0; i < 4; i++) {
        float4 zv = zp[lane + 32*i], cv = c4[lane + 32*i];
        s += zv.x*cv.x + zv.y*cv.y + zv.z*cv.z + zv.w*cv.w;
    }
    s = warpsum(s);
    if (lane == 0) g_scores[b*NN + n] = s;
}

// ---------------- K3: norm + per-batch bitonic sort on packed 64-bit keys ----
// key = (~ord(v)) << 32 | idx  → ascending u64 sort == (value desc, idx asc),
// exactly jax.lax.top_k's order. grid = 64, block = 1024.
__global__ void __launch_bounds__(1024) k_topk(float* __restrict__ out,
                                               int wr_pol, int wr_ent, int wr_idx) {
    __shared__ unsigned long long kk[NN];     // 32 KB
    __shared__ float2 red[1024];              // 8 KB
    __shared__ float  s_inv;
    int b = blockIdx.x, tid = threadIdx.x;

    // ---- inverse L2 norm of scorer row b ----
    {
        float v = 0.f;
        if (tid < FF) { float x = g_scorer[b*FF + tid]; v = x * x; }
        red[tid].x = v;
        __syncthreads();
        for (int s = 512; s; s >>= 1) {
            if (tid < s) red[tid].x += red[tid + s].x;
            __syncthreads();
        }
        if (tid == 0) s_inv = rsqrtf(red[0].x);
        __syncthreads();
    }
    float inv = s_inv;

    for (int i = tid; i < NN; i += 1024) {
        float v = g_scores[b*NN + i] * inv;
        kk[i] = ((unsigned long long)(~f2ord(v)) << 32) | (unsigned int)i;
    }
    __syncthreads();

    // bitonic sort ascending, pair-indexed (2048 pairs, 2 per thread)
    for (int k = 2; k <= NN; k <<= 1) {
        for (int j = k >> 1; j > 0; j >>= 1) {
            #pragma unroll
            for (int q = 0; q < 2; q++) {
                int p  = tid + q * 1024;
                int i1 = ((p & ~(j - 1)) << 1) | (p & (j - 1));
                int i2 = i1 | j;
                unsigned long long a = kk[i1], c = kk[i2];
                bool up = (i1 & k) == 0;
                bool sw = up ? (a > c) : (a < c);
                if (sw) { kk[i1] = c; kk[i2] = a; }
            }
            __syncthreads();
        }
    }

    float m = key2val(kk[0]);            // global max (ascending keys = desc vals)
    float se = 0.f, sxe = 0.f;
    for (int i = tid; i < NN; i += 1024) {
        float y = key2val(kk[i]) - m;
        float e = expf(y);
        se += e; sxe += y * e;
    }
    red[tid] = make_float2(se, sxe);
    __syncthreads();
    for (int s = 512; s; s >>= 1) {
        if (tid < s) { red[tid].x += red[tid+s].x; red[tid].y += red[tid+s].y; }
        __syncthreads();
    }
    if (tid < KK) {
        int   idx = (int)(unsigned int)kk[tid];
        float v   = key2val(kk[tid]);
        g_idx[b*KK + tid] = idx;
        g_tv[b*KK + tid]  = tanhf(v);
        if (wr_idx) out[OUT_IDX + b*KK + tid] = (float)idx;
    }
    if ((tid >> 5) == 0 && wr_pol) {
        float ps = key2val(kk[tid]) + key2val(kk[tid + 32])
                 + key2val(kk[tid + 64]) + key2val(kk[tid + 96]);
        ps = warpsum(ps);
        if (tid == 0) {
            float S = red[0].x, logZ = logf(S);
            out[OUT_POL + b] = ps / (float)KK - m - logZ;
        }
    }
    if (tid == 0 && wr_ent) {
        float S = red[0].x, logZ = logf(S);
        out[OUT_ENT + b] = logZ - red[0].y / S;     // entropy
    }
}

// ---------------- K4: gather + transpose: z[b][f][j] = Z[b,idx_j,f]*tanh(v_j) -
// grid = 64 batches * 8 row-groups = 512 blocks, 256 threads, 16 rows each.
__global__ void k_gather(const float* __restrict__ prev_Z) {
    __shared__ float tile[16][129];           // 129 stride: conflict-free transpose
    __shared__ int   sidx[16];
    __shared__ float stv[16];
    int b = blockIdx.x >> 3, g = blockIdx.x & 7;
    int tid = threadIdx.x;                    // 256 threads
    if (tid < 16) {
        sidx[tid] = g_idx[b*KK + g*16 + tid];
        stv[tid]  = g_tv[b*KK + g*16 + tid];
    }
    __syncthreads();
    #pragma unroll
    for (int e = tid; e < 16*128; e += 256) { // 8 front-batched loads/thread
        int jj = e >> 7, f = e & 127;
        tile[jj][f] = prev_Z[((size_t)b*NN + sidx[jj]) * FF + f] * stv[jj];
    }
    __syncthreads();
    #pragma unroll
    for (int e = tid; e < 128*16; e += 256) {
        int f = e >> 4, jj = e & 15;
        g_z[(size_t)b*16384 + f*128 + g*16 + jj] = tile[jj][f];
    }
}

// ---------------- GEMM helpers: 128x64 tile, K=128, 256 threads ----------------
#define MT_LD 129
#define XS_LD 68
#define SM_GEMM ((128*MT_LD + 128*XS_LD) * 4)

__device__ __forceinline__ void gemm_pass(const float* __restrict__ M,
                                          const float* __restrict__ Xsrc,
                                          int half, float* Mt, float* Xs,
                                          float acc[8][4], int tx, int ty, int tid) {
    // load weight transposed + X tile
    for (int e = tid; e < 128*128; e += 256) {
        int i = e >> 7, k = e & 127;
        Mt[k*MT_LD + i] = M[i*128 + k];
    }
    for (int e = tid; e < 128*64; e += 256) {
        int k = e >> 6, j = e & 63;
        Xs[k*XS_LD + j] = Xsrc[k*128 + half*64 + j];
    }
    __syncthreads();
    #pragma unroll 8
    for (int k = 0; k < 128; k++) {
        float4 xv = *(const float4*)&Xs[k*XS_LD + tx*4];
        float w[8];
        #pragma unroll
        for (int r = 0; r < 8; r++) w[r] = Mt[k*MT_LD + ty*8 + r];
        #pragma unroll
        for (int r = 0; r < 8; r++) {
            acc[r][0] += w[r]*xv.x; acc[r][1] += w[r]*xv.y;
            acc[r][2] += w[r]*xv.z; acc[r][3] += w[r]*xv.w;
        }
    }
    __syncthreads();
}

// ---------------- K5: update/reset gates + Ah = W_h @ z ----------------
// grid = 3 gates * 64 batches * 2 col-halves = 384
__global__ void __launch_bounds__(256) k_gates(
        const float* __restrict__ W_u, const float* __restrict__ U_u, const float* __restrict__ b_u,
        const float* __restrict__ W_r, const float* __restrict__ U_r, const float* __restrict__ b_r,
        const float* __restrict__ W_h, const float* __restrict__ prev_Q) {
    extern __shared__ float sm[];
    float* Mt = sm;
    float* Xs = sm + 128*MT_LD;
    int gate = blockIdx.x >> 7;
    int rem  = blockIdx.x & 127;
    int b = rem >> 1, half = rem & 1;
    int tid = threadIdx.x, tx = tid & 15, ty = tid >> 4;
    float acc[8][4];
    #pragma unroll
    for (int r = 0; r < 8; r++)
        #pragma unroll
        for (int c = 0; c < 4; c++) acc[r][c] = 0.f;

    const float* z = g_z + (size_t)b*16384;
    const float* Q = prev_Q + (size_t)b*16384;

    if (gate == 0) {
        gemm_pass(W_u, z, half, Mt, Xs, acc, tx, ty, tid);
        gemm_pass(U_u, Q, half, Mt, Xs, acc, tx, ty, tid);
    } else if (gate == 1) {
        gemm_pass(W_r, z, half, Mt, Xs, acc, tx, ty, tid);
        gemm_pass(U_r, Q, half, Mt, Xs, acc, tx, ty, tid);
    } else {
        gemm_pass(W_h, z, half, Mt, Xs, acc, tx, ty, tid);
    }

    size_t base = (size_t)b * 16384;
    #pragma unroll
    for (int r = 0; r < 8; r++) {
        int i = ty*8 + r;
        #pragma unroll
        for (int c = 0; c < 4; c++) {
            int j = half*64 + tx*4 + c;
            float p = acc[r][c];
            if (gate == 0) {
                p += b_u[i*128 + j];
                g_upd[base + i*128 + j] = 1.f / (1.f + expf(-p));
            } else if (gate == 1) {
                p += b_r[i*128 + j];
                g_rst[base + i*128 + j] = 1.f / (1.f + expf(-p));
            } else {
                g_ah[base + i*128 + j] = p;
            }
        }
    }
}

// ---------------- K6: h_cap = tanh(Ah + U_h@(r*Q) + b_h); new_Q -------------
// grid = 64 batches * 2 halves = 128
__global__ void __launch_bounds__(256) k_final(
        const float* __restrict__ U_h, const float* __restrict__ b_h,
        const float* __restrict__ prev_Q, float* __restrict__ out) {
    extern __shared__ float sm[];
    float* Mt = sm;
    float* Xs = sm + 128*MT_LD;
    int b = blockIdx.x >> 1, half = blockIdx.x & 1;
    int tid = threadIdx.x, tx = tid & 15, ty = tid >> 4;
    float acc[8][4];
    #pragma unroll
    for (int r = 0; r < 8; r++)
        #pragma unroll
        for (int c = 0; c < 4; c++) acc[r][c] = 0.f;

    size_t base = (size_t)b * 16384;
    // load Mt + X = reset .* prev_Q on the fly
    for (int e = tid; e < 128*128; e += 256) {
        int i = e >> 7, k = e & 127;
        Mt[k*MT_LD + i] = U_h[i*128 + k];
    }
    for (int e = tid; e < 128*64; e += 256) {
        int k = e >> 6, j = e & 63;
        int g = k*128 + half*64 + j;
        Xs[k*XS_LD + j] = g_rst[base + g] * prev_Q[base + g];
    }
    __syncthreads();
    #pragma unroll 8
    for (int k = 0; k < 128; k++) {
        float4 xv = *(const float4*)&Xs[k*XS_LD + tx*4];
        float w[8];
        #pragma unroll
        for (int r = 0; r < 8; r++) w[r] = Mt[k*MT_LD + ty*8 + r];
        #pragma unroll
        for (int r = 0; r < 8; r++) {
            acc[r][0] += w[r]*xv.x; acc[r][1] += w[r]*xv.y;
            acc[r][2] += w[r]*xv.z; acc[r][3] += w[r]*xv.w;
        }
    }
    #pragma unroll
    for (int r = 0; r < 8; r++) {
        int i = ty*8 + r;
        #pragma unroll
        for (int c = 0; c < 4; c++) {
            int j = half*64 + tx*4 + c;
            size_t idx = base + i*128 + j;
            float h = tanhf(acc[r][c] + g_ah[idx] + b_h[i*128 + j]);
            float u = g_upd[idx];
            float q = prev_Q[idx];
            out[OUT_Q + idx] = (1.f - u)*q + u*h;
        }
    }
}

// ---------------- host ----------------
extern "C" void kernel_launch(void* const* d_in, const int* in_sizes, int n_in,
                              void* d_out, int out_size) {
    const float* prev_Q = (const float*)d_in[0];
    const float* prev_Z = (const float*)d_in[1];
    const float* ht     = (const float*)d_in[2];
    const float* W_map  = (const float*)d_in[3];
    const float* b_map  = (const float*)d_in[4];
    const float* W_u    = (const float*)d_in[5];
    const float* U_u    = (const float*)d_in[6];
    const float* b_u    = (const float*)d_in[7];
    const float* W_r    = (const float*)d_in[8];
    const float* U_r    = (const float*)d_in[9];
    const float* b_r    = (const float*)d_in[10];
    const float* W_h    = (const float*)d_in[11];
    const float* U_h    = (const float*)d_in[12];
    const float* b_h    = (const float*)d_in[13];
    float* out = (float*)d_out;

    // per-section guards: write a section only if out_size covers it
    int wr_pol    = (out_size >= OUT_SCORER) ? 1 : 0;
    int wr_scorer = (out_size >= OUT_ENT)    ? 1 : 0;
    int wr_ent    = (out_size >= OUT_IDX)    ? 1 : 0;
    int wr_idx    = (out_size >= OUT_FULL)   ? 1 : 0;

    // no static guards (harness rule): idempotent, called every time
    cudaFuncSetAttribute(k_gates, cudaFuncAttributeMaxDynamicSharedMemorySize, SM_GEMM);
    cudaFuncSetAttribute(k_final, cudaFuncAttributeMaxDynamicSharedMemorySize, SM_GEMM);

    k_scorer <<<(BB*FF)/8, 256>>>(ht, W_map, b_map, out, wr_scorer);
    k_scores <<<BB*(NN/8), 256>>>(prev_Z);
    k_topk   <<<BB, 1024>>>(out, wr_pol, wr_ent, wr_idx);
    k_gather <<<BB*8, 256>>>(prev_Z);
    k_gates  <<<384, 256, SM_GEMM>>>(W_u, U_u, b_u, W_r, U_r, b_r, W_h, prev_Q);
    k_final  <<<128, 256, SM_GEMM>>>(U_h, b_h, prev_Q, out);
}